// round 11
// baseline (speedup 1.0000x reference)
#include <cuda_runtime.h>
#include <cuda_bf16.h>
#include <cstdint>

#define BB 8
#define SS 4096
#define HH 1024
#define KK 2048   // K = 0.5 * S

__device__ float    g_scores[BB * SS];   // sigmoid(logit)
__device__ int      g_hist[BB * 256];    // pass-0 bins; re-zeroed by emit kernel
__device__ int      g_ticket[BB];        // last-block tickets; re-zeroed by emit
__device__ uint32_t g_thresh[BB];        // K-th largest key (overwritten each call)
__device__ int      g_cut[BB];           // tie cut index (overwritten each call)

__device__ __forceinline__ uint32_t orderable(float f) {
    uint32_t u = __float_as_uint(f);
    return u ^ ((u >> 31) ? 0xFFFFFFFFu : 0x80000000u);
}

// ---------------------------------------------------------------------------
// Fused kernel: GEMV (2 tokens/warp, 16 tokens/block, 256 blocks/row) +
// per-row radix top-K threshold computed by the LAST block of each row.
// ---------------------------------------------------------------------------
__global__ __launch_bounds__(256) void router_fused_kernel(
    const float* __restrict__ x, const float* __restrict__ w,
    float* __restrict__ scores, int* __restrict__ hist_g,
    int* __restrict__ ticket_g, uint32_t* __restrict__ thresh_g,
    int* __restrict__ cut_g)
{
    __shared__ int      s_last;
    __shared__ int      s_hist[256];
    __shared__ uint32_t s_prefix;
    __shared__ int      s_kk, s_E, s_cut;

    const int tid  = threadIdx.x;
    const int lane = tid & 31;
    const int row  = blockIdx.x >> 8;                 // 256 blocks per row

    // ---- GEMV: this block's 16 tokens ----
    {
        int gw = (blockIdx.x * 256 + tid) >> 5;       // global warp
        int r0 = gw * 2;

        const float4* xp0 = reinterpret_cast<const float4*>(x + (size_t)r0 * HH);
        const float4* xp1 = xp0 + (HH / 4);
        const float4* wp  = reinterpret_cast<const float4*>(w);

        float a0 = 0.0f, a1 = 0.0f;
#pragma unroll
        for (int i = 0; i < 8; i++) {                 // 8 * 32 * 4 = 1024 = H
            int idx = lane + i * 32;
            float4 wv = __ldg(&wp[idx]);
            float4 u  = xp0[idx];
            float4 t  = xp1[idx];
            a0 = fmaf(u.x, wv.x, a0); a0 = fmaf(u.y, wv.y, a0);
            a0 = fmaf(u.z, wv.z, a0); a0 = fmaf(u.w, wv.w, a0);
            a1 = fmaf(t.x, wv.x, a1); a1 = fmaf(t.y, wv.y, a1);
            a1 = fmaf(t.z, wv.z, a1); a1 = fmaf(t.w, wv.w, a1);
        }
#pragma unroll
        for (int o = 16; o; o >>= 1) {
            a0 += __shfl_xor_sync(0xFFFFFFFFu, a0, o);
            a1 += __shfl_xor_sync(0xFFFFFFFFu, a1, o);
        }
        if (lane == 0) {
            float s0 = 1.0f / (1.0f + expf(-a0));
            float s1 = 1.0f / (1.0f + expf(-a1));
            scores[r0]     = s0;
            scores[r0 + 1] = s1;
            int* hrow = hist_g + row * 256;
            atomicAdd(&hrow[orderable(s0) >> 24], 1);
            atomicAdd(&hrow[orderable(s1) >> 24], 1);
        }
    }

    // ---- Last-block ticket ----
    __syncthreads();
    if (tid == 0) {
        __threadfence();                               // scores + hist visible
        s_last = (atomicAdd(&ticket_g[row], 1) == 255);
    }
    __syncthreads();
    if (!s_last) return;

    // =======================================================================
    // Row selection (only the last block of this row runs this; for rows
    // 0..B-2 it overlaps the remaining GEMV work on the rest of the chip).
    // =======================================================================
    const float* rowp = scores + row * SS;

    // Load the full row: 16 elements/thread (4 float4s), keys in registers.
    uint32_t k[16];
#pragma unroll
    for (int q = 0; q < 4; q++) {
        float4 lv = *reinterpret_cast<const float4*>(rowp + tid * 16 + q * 4);
        k[q * 4 + 0] = orderable(lv.x);
        k[q * 4 + 1] = orderable(lv.y);
        k[q * 4 + 2] = orderable(lv.z);
        k[q * 4 + 3] = orderable(lv.w);
    }

    // ---- Radix pass 0: warp-scan the precomputed global histogram ----
    if (tid < 32) {
        const int* gh = hist_g + row * 256;
        int h[8];
        int part = 0;
#pragma unroll
        for (int j = 0; j < 8; j++) {
            h[j] = gh[255 - (tid * 8 + j)];
            part += h[j];
        }
        int inc = part;
#pragma unroll
        for (int o = 1; o < 32; o <<= 1) {
            int t = __shfl_up_sync(0xFFFFFFFFu, inc, o);
            if (tid >= o) inc += t;
        }
        const int excl = inc - part;
        if (excl < KK && excl + part >= KK) {
            int acc = excl;
#pragma unroll
            for (int j = 0; j < 8; j++) {
                if (acc + h[j] >= KK) {
                    int d = 255 - (tid * 8 + j);
                    s_prefix = (uint32_t)d << 24;
                    s_kk = KK - acc;
                    s_E  = h[j];
                    break;
                }
                acc += h[j];
            }
        }
    }
    __syncthreads();

    // ---- Radix passes 1-3 ----
#pragma unroll
    for (int pass = 0; pass < 3; pass++) {
        const int shift = 16 - pass * 8;
        const uint32_t pmask = 0xFFFFFFFFu << (shift + 8);

        s_hist[tid] = 0;
        __syncthreads();

        const uint32_t prefix = s_prefix;
#pragma unroll
        for (int i = 0; i < 16; i++)
            if ((k[i] & pmask) == prefix)
                atomicAdd(&s_hist[(k[i] >> shift) & 0xFF], 1);
        __syncthreads();

        if (tid < 32) {
            const int kk = s_kk;
            int h[8];
            int part = 0;
#pragma unroll
            for (int j = 0; j < 8; j++) {
                h[j] = s_hist[255 - (tid * 8 + j)];
                part += h[j];
            }
            int inc = part;
#pragma unroll
            for (int o = 1; o < 32; o <<= 1) {
                int t = __shfl_up_sync(0xFFFFFFFFu, inc, o);
                if (tid >= o) inc += t;
            }
            const int excl = inc - part;
            if (excl < kk && excl + part >= kk) {
                int acc = excl;
#pragma unroll
                for (int j = 0; j < 8; j++) {
                    if (acc + h[j] >= kk) {
                        int d = 255 - (tid * 8 + j);
                        s_prefix = prefix | ((uint32_t)d << shift);
                        s_kk = kk - acc;
                        s_E  = h[j];
                        break;
                    }
                    acc += h[j];
                }
            }
        }
        __syncthreads();
    }

    const uint32_t thresh = s_prefix;   // exact K-th largest key
    const int T = s_kk;
    const int E = s_E;

    // Rare tie path (E > T): index of the T-th equal key, warp-parallel.
    if (tid < 32) {
        if (E > T) {
            int need = T, cut = SS;
            for (int bs = 0; bs < SS; bs += 32) {
                uint32_t kk2 = orderable(rowp[bs + tid]);
                uint32_t mask = __ballot_sync(0xFFFFFFFFu, kk2 == thresh);
                int c = __popc(mask);
                if (c >= need) {
                    uint32_t mm = mask;
                    for (int t = 1; t < need; t++) mm &= mm - 1;
                    cut = bs + __ffs(mm) - 1;
                    break;
                }
                need -= c;
            }
            if (tid == 0) s_cut = cut;
        } else {
            if (tid == 0) s_cut = SS;
        }
    }
    __syncthreads();

    if (tid == 0) {
        thresh_g[row] = thresh;
        cut_g[row]    = s_cut;
        __threadfence();                 // publish before kernel end (belt+braces)
    }
}

// ---------------------------------------------------------------------------
// Wide emit: 32 blocks x 256 threads, one float4 of weights + one of mask
// per thread. Also re-zeroes g_hist / g_ticket for the next graph replay.
// ---------------------------------------------------------------------------
__global__ __launch_bounds__(256) void emit_kernel(
    const float* __restrict__ scores, const uint32_t* __restrict__ thresh_g,
    const int* __restrict__ cut_g, int* __restrict__ hist_g,
    int* __restrict__ ticket_g, float* __restrict__ out, int out_size)
{
    const int tid = threadIdx.x;
    const int e4  = blockIdx.x * 256 + tid;       // float4 index
    const int e   = e4 * 4;                       // element index
    const int b   = e >> 12;                      // row (SS = 4096)

    // housekeeping: reset scratch state for next replay
    if (blockIdx.x < 8) {
        hist_g[blockIdx.x * 256 + tid] = 0;
        if (tid == 0) ticket_g[blockIdx.x] = 0;
    }

    const uint32_t thresh = thresh_g[b];
    const int      cut    = cut_g[b];

    float4 lv = *reinterpret_cast<const float4*>(scores + e);
    float v[4] = {lv.x, lv.y, lv.z, lv.w};
    float wv4[4], mv4[4];
#pragma unroll
    for (int i = 0; i < 4; i++) {
        uint32_t kk = orderable(v[i]);
        int s = (e & (SS - 1)) + i;               // in-row index
        bool m = (kk > thresh) || (kk == thresh && s <= cut);
        wv4[i] = m ? v[i] : 0.0f;
        mv4[i] = m ? 1.0f : 0.0f;
    }
    *reinterpret_cast<float4*>(out + e) =
        make_float4(wv4[0], wv4[1], wv4[2], wv4[3]);
    if (out_size >= 2 * BB * SS)
        *reinterpret_cast<float4*>(out + BB * SS + e) =
            make_float4(mv4[0], mv4[1], mv4[2], mv4[3]);
}

extern "C" void kernel_launch(void* const* d_in, const int* in_sizes, int n_in,
                              void* d_out, int out_size)
{
    const float* hidden = (const float*)d_in[0];
    const float* w      = (const float*)d_in[1];
    float* out = (float*)d_out;

    float*    scores = nullptr;
    int*      hist   = nullptr;
    int*      ticket = nullptr;
    uint32_t* thr    = nullptr;
    int*      cut    = nullptr;
    cudaGetSymbolAddress((void**)&scores, g_scores);
    cudaGetSymbolAddress((void**)&hist,   g_hist);
    cudaGetSymbolAddress((void**)&ticket, g_ticket);
    cudaGetSymbolAddress((void**)&thr,    g_thresh);
    cudaGetSymbolAddress((void**)&cut,    g_cut);

    router_fused_kernel<<<BB * 256, 256>>>(hidden, w, scores, hist,
                                           ticket, thr, cut);
    emit_kernel<<<(BB * SS) / (256 * 4), 256>>>(scores, thr, cut, hist,
                                                ticket, out, out_size);
}